// round 2
// baseline (speedup 1.0000x reference)
#include <cuda_runtime.h>
#include <cuda_bf16.h>
#include <cstdint>

// Problem constants (fixed by the dataset)
#define NNODES 50000
#define NEDGES 400000
#define EP     (NNODES + NEDGES)   // edges incl. self-loops = 450000
#define FIN    128
#define HID    64
#define H1DIM  512                 // 8 heads * 64
#define NEG_SLOPE 0.2f

// ------------------------- scratch (static device memory) -------------------
__device__ float g_h1[(size_t)NNODES * H1DIM];     // x @ W1           [N,512]
__device__ float g_out1[(size_t)NNODES * H1DIM];   // layer1 agg       [N,512]
__device__ float g_alsrc1[(size_t)NNODES * 8];
__device__ float g_aldst1[(size_t)NNODES * 8];
__device__ float g_denom1[(size_t)NNODES * 8];
__device__ float g_ex1[(size_t)EP * 8];

__device__ float g_h2[(size_t)NNODES * HID];       // relu(out1+b1)@W2 [N,64]
__device__ float g_out2[(size_t)NNODES * HID];
__device__ float g_alsrc2[NNODES];
__device__ float g_aldst2[NNODES];
__device__ float g_denom2[NNODES];
__device__ float g_ex2[EP];

// ------------------------- helpers ------------------------------------------
__device__ __forceinline__ void red_add_v4(float* p, float4 v) {
    asm volatile("red.global.add.v4.f32 [%0], {%1,%2,%3,%4};"
                 :: "l"(p), "f"(v.x), "f"(v.y), "f"(v.z), "f"(v.w)
                 : "memory");
}

enum ZeroWhat { Z_OUT1, Z_DEN1, Z_OUT2, Z_DEN2 };
template <ZeroWhat W>
__global__ void zero_kernel() {
    size_t n4;
    float4* p;
    if (W == Z_OUT1) { p = (float4*)g_out1;   n4 = (size_t)NNODES * H1DIM / 4; }
    if (W == Z_DEN1) { p = (float4*)g_denom1; n4 = (size_t)NNODES * 8 / 4; }
    if (W == Z_OUT2) { p = (float4*)g_out2;   n4 = (size_t)NNODES * HID / 4; }
    if (W == Z_DEN2) { p = (float4*)g_denom2; n4 = (size_t)NNODES / 4; }
    size_t i = (size_t)blockIdx.x * blockDim.x + threadIdx.x;
    size_t stride = (size_t)gridDim.x * blockDim.x;
    float4 z = make_float4(0.f, 0.f, 0.f, 0.f);
    for (; i < n4; i += stride) p[i] = z;
}

// ------------------------- SGEMM (register tiled) ----------------------------
// C[M,N] = op(A)[M,K] @ B[K,N];  RELU_BIAS: A elem -> max(A + bias[k], 0)
template <bool RELU_BIAS>
__global__ __launch_bounds__(256, 3)
void sgemm_kernel(int M, int N, int K,
                  const float* __restrict__ A,
                  const float* __restrict__ B,
                  const float* __restrict__ bias,
                  float* __restrict__ C)
{
    constexpr int BM = 128, BN = 64, BK = 16, TM = 8, TN = 4;
    __shared__ float As[BK][BM];
    __shared__ float Bs[BK][BN];

    const int tid = threadIdx.x;
    const int block_row = blockIdx.y * BM;
    const int block_col = blockIdx.x * BN;

    const int tcol = tid % (BN / TN);   // 0..15
    const int trow = tid / (BN / TN);   // 0..15

    const int a_row = tid / 4;          // 0..63
    const int a_col = (tid % 4) * 4;    // 0,4,8,12
    const int b_row = tid / 16;         // 0..15
    const int b_col = (tid % 16) * 4;   // 0..60

    float acc[TM][TN];
#pragma unroll
    for (int i = 0; i < TM; i++)
#pragma unroll
        for (int j = 0; j < TN; j++) acc[i][j] = 0.f;

    for (int k0 = 0; k0 < K; k0 += BK) {
        // load A tile (transposed into smem)
#pragma unroll
        for (int r = 0; r < 2; r++) {
            int row  = a_row + r * 64;
            int grow = block_row + row;
            float4 v = make_float4(0.f, 0.f, 0.f, 0.f);
            if (grow < M) {
                v = *(const float4*)&A[(size_t)grow * K + k0 + a_col];
                if (RELU_BIAS) {
                    const float4 b = *(const float4*)&bias[k0 + a_col];
                    v.x = fmaxf(v.x + b.x, 0.f);
                    v.y = fmaxf(v.y + b.y, 0.f);
                    v.z = fmaxf(v.z + b.z, 0.f);
                    v.w = fmaxf(v.w + b.w, 0.f);
                }
            }
            As[a_col + 0][row] = v.x;
            As[a_col + 1][row] = v.y;
            As[a_col + 2][row] = v.z;
            As[a_col + 3][row] = v.w;
        }
        // load B tile
        {
            float4 v = *(const float4*)&B[(size_t)(k0 + b_row) * N + block_col + b_col];
            *(float4*)&Bs[b_row][b_col] = v;
        }
        __syncthreads();

#pragma unroll
        for (int kk = 0; kk < BK; kk++) {
            float ar[TM], br[TN];
#pragma unroll
            for (int i = 0; i < TM; i++) ar[i] = As[kk][trow * TM + i];
#pragma unroll
            for (int j = 0; j < TN; j++) br[j] = Bs[kk][tcol * TN + j];
#pragma unroll
            for (int i = 0; i < TM; i++)
#pragma unroll
                for (int j = 0; j < TN; j++) acc[i][j] += ar[i] * br[j];
        }
        __syncthreads();
    }

#pragma unroll
    for (int i = 0; i < TM; i++) {
        int grow = block_row + trow * TM + i;
        if (grow >= M) continue;
        float4 v = make_float4(acc[i][0], acc[i][1], acc[i][2], acc[i][3]);
        *(float4*)&C[(size_t)grow * N + block_col + tcol * TN] = v;
    }
}

// ------------------------- attention dot products ----------------------------
// one thread per (node*heads + head); h row = &h[i*64]; a vectors indexed by head&mask
__global__ void att_dots_kernel(const float* __restrict__ h,
                                const float* __restrict__ a_src,
                                const float* __restrict__ a_dst,
                                float* __restrict__ al_src,
                                float* __restrict__ al_dst,
                                int total, int head_mask)
{
    int i = blockIdx.x * blockDim.x + threadIdx.x;
    if (i >= total) return;
    int head = i & head_mask;
    const float4* hp = (const float4*)&h[(size_t)i * HID];
    const float4* as = (const float4*)&a_src[head * HID];
    const float4* ad = (const float4*)&a_dst[head * HID];
    float ss = 0.f, sd = 0.f;
#pragma unroll
    for (int k = 0; k < HID / 4; k++) {
        float4 v = hp[k], a1 = as[k], a2 = ad[k];
        ss += v.x * a1.x + v.y * a1.y + v.z * a1.z + v.w * a1.w;
        sd += v.x * a2.x + v.y * a2.y + v.z * a2.z + v.w * a2.w;
    }
    al_src[i] = ss;
    al_dst[i] = sd;
}

// ------------------------- layer1 edge softmax numerator/denominator ---------
// NOTE: edge_index is int32 on device (JAX default x64-disabled).
__global__ void edge_den1_kernel(const int* __restrict__ ei)
{
    int e = blockIdx.x * blockDim.x + threadIdx.x;
    if (e >= EP) return;
    int s, d;
    if (e < NEDGES) { s = ei[e]; d = ei[NEDGES + e]; }
    else            { s = d = e - NEDGES; }

    float4 s0 = *(const float4*)&g_alsrc1[(size_t)s * 8];
    float4 s1 = *(const float4*)&g_alsrc1[(size_t)s * 8 + 4];
    float4 d0 = *(const float4*)&g_aldst1[(size_t)d * 8];
    float4 d1 = *(const float4*)&g_aldst1[(size_t)d * 8 + 4];

    float v[8] = { s0.x + d0.x, s0.y + d0.y, s0.z + d0.z, s0.w + d0.w,
                   s1.x + d1.x, s1.y + d1.y, s1.z + d1.z, s1.w + d1.w };
    float exv[8];
#pragma unroll
    for (int h = 0; h < 8; h++) {
        float t = v[h];
        t = (t > 0.f) ? t : NEG_SLOPE * t;
        t = __expf(t);
        exv[h] = t;
        atomicAdd(&g_denom1[(size_t)d * 8 + h], t);
    }
    *(float4*)&g_ex1[(size_t)e * 8]     = make_float4(exv[0], exv[1], exv[2], exv[3]);
    *(float4*)&g_ex1[(size_t)e * 8 + 4] = make_float4(exv[4], exv[5], exv[6], exv[7]);
}

// ------------------------- layer1 message scatter (warp per edge) ------------
__global__ __launch_bounds__(256)
void scatter1_kernel(const int* __restrict__ ei)
{
    int warp = (blockIdx.x * blockDim.x + threadIdx.x) >> 5;
    int lane = threadIdx.x & 31;
    if (warp >= EP) return;
    int s, d;
    if (warp < NEDGES) { s = ei[warp]; d = ei[NEDGES + warp]; }
    else               { s = d = warp - NEDGES; }

    const float* hsrc = &g_h1[(size_t)s * H1DIM];
    float* odst = &g_out1[(size_t)d * H1DIM];
    const float* exe = &g_ex1[(size_t)warp * 8];
    const float* dnd = &g_denom1[(size_t)d * 8];

#pragma unroll
    for (int it = 0; it < 4; it++) {
        int c4 = it * 32 + lane;        // float4 index 0..127
        int h  = c4 >> 4;               // head = c4 / 16
        float alpha = __ldg(&exe[h]) / __ldg(&dnd[h]);
        float4 v = *(const float4*)&hsrc[c4 * 4];
        v.x *= alpha; v.y *= alpha; v.z *= alpha; v.w *= alpha;
        red_add_v4(&odst[c4 * 4], v);
    }
}

// ------------------------- layer2 edge softmax -------------------------------
__global__ void edge_den2_kernel(const int* __restrict__ ei)
{
    int e = blockIdx.x * blockDim.x + threadIdx.x;
    if (e >= EP) return;
    int s, d;
    if (e < NEDGES) { s = ei[e]; d = ei[NEDGES + e]; }
    else            { s = d = e - NEDGES; }
    float t = g_alsrc2[s] + g_aldst2[d];
    t = (t > 0.f) ? t : NEG_SLOPE * t;
    t = __expf(t);
    g_ex2[e] = t;
    atomicAdd(&g_denom2[d], t);
}

// ------------------------- layer2 message scatter (16 threads per edge) ------
__global__ __launch_bounds__(256)
void scatter2_kernel(const int* __restrict__ ei)
{
    int gt = blockIdx.x * blockDim.x + threadIdx.x;
    int e  = gt >> 4;
    int l  = gt & 15;
    if (e >= EP) return;
    int s, d;
    if (e < NEDGES) { s = ei[e]; d = ei[NEDGES + e]; }
    else            { s = d = e - NEDGES; }
    float alpha = __ldg(&g_ex2[e]) / __ldg(&g_denom2[d]);
    float4 v = *(const float4*)&g_h2[(size_t)s * HID + l * 4];
    v.x *= alpha; v.y *= alpha; v.z *= alpha; v.w *= alpha;
    red_add_v4(&g_out2[(size_t)d * HID + l * 4], v);
}

// ------------------------- final: relu(out2+b2) @ Wc + bc ---------------------
__global__ void final_kernel(const float* __restrict__ b2,
                             const float* __restrict__ Wc,
                             const float* __restrict__ bc,
                             float* __restrict__ out)
{
    int warp = (blockIdx.x * blockDim.x + threadIdx.x) >> 5;
    int lane = threadIdx.x & 31;
    if (warp >= NNODES) return;
    float acc = 0.f;
#pragma unroll
    for (int k = lane; k < HID; k += 32) {
        float v = g_out2[(size_t)warp * HID + k] + b2[k];
        v = fmaxf(v, 0.f);
        acc += v * Wc[k];
    }
#pragma unroll
    for (int o = 16; o; o >>= 1) acc += __shfl_down_sync(0xffffffffu, acc, o);
    if (lane == 0) out[warp] = acc + bc[0];
}

// ------------------------- host launcher --------------------------------------
extern "C" void kernel_launch(void* const* d_in, const int* in_sizes, int n_in,
                              void* d_out, int out_size)
{
    const float* x      = (const float*)d_in[0];
    const int*   ei     = (const int*)d_in[1];     // int32 (JAX x64 disabled)
    const float* W1     = (const float*)d_in[2];
    const float* a_src1 = (const float*)d_in[3];
    const float* a_dst1 = (const float*)d_in[4];
    const float* b1     = (const float*)d_in[5];
    const float* W2     = (const float*)d_in[6];
    const float* a_src2 = (const float*)d_in[7];
    const float* a_dst2 = (const float*)d_in[8];
    const float* b2     = (const float*)d_in[9];
    const float* Wc     = (const float*)d_in[10];
    const float* bc     = (const float*)d_in[11];
    float* out = (float*)d_out;

    // device symbol addresses (via device-side reference; no runtime API needed)
    float* h1   = nullptr;  // kernels use globals directly; these are for sgemm args
    float* out1 = nullptr;
    float* h2   = nullptr;
    // We still need raw pointers for the generic sgemm/att kernels; take them
    // from the device symbols. cudaGetSymbolAddress enqueues no work and is
    // capture-safe, but we avoid even that by using a tiny trampoline:
    static float* s_h1 = nullptr, *s_out1 = nullptr, *s_h2 = nullptr,
                * s_alsrc1 = nullptr, *s_aldst1 = nullptr,
                * s_alsrc2 = nullptr, *s_aldst2 = nullptr;
    if (!s_h1) {  // address lookup only; deterministic, does no device work
        cudaGetSymbolAddress((void**)&s_h1,     g_h1);
        cudaGetSymbolAddress((void**)&s_out1,   g_out1);
        cudaGetSymbolAddress((void**)&s_h2,     g_h2);
        cudaGetSymbolAddress((void**)&s_alsrc1, g_alsrc1);
        cudaGetSymbolAddress((void**)&s_aldst1, g_aldst1);
        cudaGetSymbolAddress((void**)&s_alsrc2, g_alsrc2);
        cudaGetSymbolAddress((void**)&s_aldst2, g_aldst2);
    }
    h1 = s_h1; out1 = s_out1; h2 = s_h2;

    // zero accumulators
    zero_kernel<Z_OUT1><<<4096, 256>>>();
    zero_kernel<Z_DEN1><<<256,  256>>>();
    zero_kernel<Z_OUT2><<<1024, 256>>>();
    zero_kernel<Z_DEN2><<<64,   256>>>();

    // GEMM1: h1 = x @ W1   [50000,128]x[128,512]
    {
        dim3 grid(H1DIM / 64, (NNODES + 127) / 128);
        sgemm_kernel<false><<<grid, 256>>>(NNODES, H1DIM, FIN, x, W1, nullptr, h1);
    }
    // attention dots layer 1
    att_dots_kernel<<<(NNODES * 8 + 255) / 256, 256>>>(h1, a_src1, a_dst1,
                                                       s_alsrc1, s_aldst1, NNODES * 8, 7);
    // edge softmax denominator layer 1
    edge_den1_kernel<<<(EP + 255) / 256, 256>>>(ei);
    // scatter layer 1 (warp per edge)
    scatter1_kernel<<<(EP * 32 + 255) / 256, 256>>>(ei);

    // GEMM2: h2 = relu(out1 + b1) @ W2   [50000,512]x[512,64]
    {
        dim3 grid(HID / 64, (NNODES + 127) / 128);
        sgemm_kernel<true><<<grid, 256>>>(NNODES, HID, H1DIM, out1, W2, b1, h2);
    }
    // attention dots layer 2 (1 head)
    att_dots_kernel<<<(NNODES + 255) / 256, 256>>>(h2, a_src2, a_dst2,
                                                   s_alsrc2, s_aldst2, NNODES, 0);
    // edge softmax denominator layer 2
    edge_den2_kernel<<<(EP + 255) / 256, 256>>>(ei);
    // scatter layer 2 (16 threads per edge)
    scatter2_kernel<<<(EP * 16 + 255) / 256, 256>>>(ei);

    // final projection
    final_kernel<<<(NNODES * 32 + 255) / 256, 256>>>(b2, Wc, bc, out);
}

// round 3
// speedup vs baseline: 1.3775x; 1.3775x over previous
#include <cuda_runtime.h>
#include <cuda_fp16.h>
#include <cstdint>

// Problem constants (fixed by the dataset)
#define NNODES 50000
#define NEDGES 400000
#define EP     (NNODES + NEDGES)   // edges incl. self-loops = 450000
#define FIN    128
#define HID    64
#define H1DIM  512                 // 8 heads * 64
#define NEG_SLOPE 0.2f

// ------------------------- scratch (static device memory) -------------------
__device__ __half g_h1h[(size_t)NNODES * H1DIM];   // fp16 copy of x@W1
__device__ float  g_out1[(size_t)NNODES * H1DIM];  // layer1 agg (fp32 atomics)
__device__ float  g_alsrc1[(size_t)NNODES * 8];
__device__ float  g_aldst1[(size_t)NNODES * 8];
__device__ float  g_denom1[(size_t)NNODES * 8];
__device__ float  g_ex1[(size_t)EP * 8];

__device__ __half g_h2h[(size_t)NNODES * HID];     // fp16 copy of layer2 features
__device__ float  g_out2[(size_t)NNODES * HID];
__device__ float  g_alsrc2[NNODES];
__device__ float  g_aldst2[NNODES];
__device__ float  g_denom2[NNODES];
__device__ float  g_ex2[EP];

// ------------------------- helpers ------------------------------------------
__device__ __forceinline__ void red_add_v4(float* p, float4 v) {
    asm volatile("red.global.add.v4.f32 [%0], {%1,%2,%3,%4};"
                 :: "l"(p), "f"(v.x), "f"(v.y), "f"(v.z), "f"(v.w)
                 : "memory");
}

__device__ __forceinline__ uint32_t f2tf32(float f) {
    uint32_t r;
    asm("cvt.rna.tf32.f32 %0, %1;" : "=r"(r) : "f"(f));
    return r;
}

__device__ __forceinline__ void mma_tf32(float d[4], const uint32_t a[4], const uint32_t b[2]) {
    asm volatile(
        "mma.sync.aligned.m16n8k8.row.col.f32.tf32.tf32.f32 "
        "{%0,%1,%2,%3}, {%4,%5,%6,%7}, {%8,%9}, {%0,%1,%2,%3};"
        : "+f"(d[0]), "+f"(d[1]), "+f"(d[2]), "+f"(d[3])
        : "r"(a[0]), "r"(a[1]), "r"(a[2]), "r"(a[3]), "r"(b[0]), "r"(b[1]));
}

// ------------------------- zero kernels --------------------------------------
__global__ void zero_big_kernel() {
    // out1 (6.4M float4) + out2 (0.8M float4)
    const size_t n1 = (size_t)NNODES * H1DIM / 4;
    const size_t n2 = (size_t)NNODES * HID / 4;
    float4 z = make_float4(0.f, 0.f, 0.f, 0.f);
    size_t i = (size_t)blockIdx.x * blockDim.x + threadIdx.x;
    size_t stride = (size_t)gridDim.x * blockDim.x;
    for (; i < n1 + n2; i += stride) {
        if (i < n1) ((float4*)g_out1)[i] = z;
        else        ((float4*)g_out2)[i - n1] = z;
    }
}

__global__ void zero_small_kernel() {
    int i = blockIdx.x * blockDim.x + threadIdx.x;
    if (i < NNODES * 8) { g_denom1[i] = 0.f; g_alsrc1[i] = 0.f; g_aldst1[i] = 0.f; }
    if (i < NNODES)     { g_denom2[i] = 0.f; g_alsrc2[i] = 0.f; g_aldst2[i] = 0.f; }
}

// ------------------------- TF32 tensor-core GEMM with fused attention dots ---
// C[M,N] = op(A)[M,K] @ B[K,N];  op = relu(A + bias[k]) if RELU_BIAS.
// Writes fp16 C to Ch; accumulates per-(row,head) dot(a_src, C_row_head) into
// alsrc/aldst via red.f32 (must be pre-zeroed). HEADS = N/64.
template<int BM, int BN, int BK, int WM, int WN, int HEADS, bool RELU_BIAS, int K, int N>
__global__ __launch_bounds__(256)
void gemm_tf32_att(int M,
                   const float* __restrict__ A,
                   const float* __restrict__ B,
                   const float* __restrict__ bias,
                   const float* __restrict__ a_src,
                   const float* __restrict__ a_dst,
                   __half* __restrict__ Ch,
                   float* __restrict__ alsrc,
                   float* __restrict__ aldst)
{
    constexpr int WARPS_N = BN / WN;
    constexpr int MT = WM / 16;
    constexpr int NT = WN / 8;
    constexpr int AS_STRIDE = BK + 4;   // As[m][k], stride chosen conflict-free
    constexpr int BS_STRIDE = BN + 8;   // Bs[k][n]

    __shared__ uint32_t As[BM * AS_STRIDE];
    __shared__ uint32_t Bs[BK * BS_STRIDE];

    const int tid  = threadIdx.x;
    const int lane = tid & 31;
    const int warp = tid >> 5;
    const int block_row = blockIdx.y * BM;
    const int block_col = blockIdx.x * BN;
    const int wm = (warp / WARPS_N) * WM;
    const int wn = (warp % WARPS_N) * WN;
    const int g   = lane >> 2;
    const int tig = lane & 3;

    float acc[MT][NT][4];
#pragma unroll
    for (int mt = 0; mt < MT; mt++)
#pragma unroll
        for (int nt = 0; nt < NT; nt++)
#pragma unroll
            for (int j = 0; j < 4; j++) acc[mt][nt][j] = 0.f;

    for (int k0 = 0; k0 < K; k0 += BK) {
        // ---- load A tile (row-major [m][k]) ----
        constexpr int A_F4 = BM * BK / 1024;
#pragma unroll
        for (int i = 0; i < A_F4; i++) {
            int idx = i * 256 + tid;
            int ar  = idx / (BK / 4);
            int ac4 = idx % (BK / 4);
            int grow = block_row + ar;
            float4 v = make_float4(0.f, 0.f, 0.f, 0.f);
            if (grow < M) {
                v = *(const float4*)&A[(size_t)grow * K + k0 + ac4 * 4];
                if (RELU_BIAS) {
                    const float4 b = *(const float4*)&bias[k0 + ac4 * 4];
                    v.x = fmaxf(v.x + b.x, 0.f);
                    v.y = fmaxf(v.y + b.y, 0.f);
                    v.z = fmaxf(v.z + b.z, 0.f);
                    v.w = fmaxf(v.w + b.w, 0.f);
                }
            }
            uint4 t = make_uint4(f2tf32(v.x), f2tf32(v.y), f2tf32(v.z), f2tf32(v.w));
            *(uint4*)&As[ar * AS_STRIDE + ac4 * 4] = t;
        }
        // ---- load B tile ([k][n]) ----
        constexpr int B_F4 = BK * BN / 1024;
#pragma unroll
        for (int i = 0; i < B_F4; i++) {
            int idx = i * 256 + tid;
            int br  = idx / (BN / 4);
            int bc4 = idx % (BN / 4);
            float4 v = *(const float4*)&B[(size_t)(k0 + br) * N + block_col + bc4 * 4];
            uint4 t = make_uint4(f2tf32(v.x), f2tf32(v.y), f2tf32(v.z), f2tf32(v.w));
            *(uint4*)&Bs[br * BS_STRIDE + bc4 * 4] = t;
        }
        __syncthreads();

        // ---- mma mainloop ----
#pragma unroll
        for (int ks = 0; ks < BK / 8; ks++) {
            uint32_t af[MT][4], bf[NT][2];
#pragma unroll
            for (int mt = 0; mt < MT; mt++) {
                int m0 = wm + mt * 16 + g;
                af[mt][0] = As[m0 * AS_STRIDE + ks * 8 + tig];
                af[mt][1] = As[(m0 + 8) * AS_STRIDE + ks * 8 + tig];
                af[mt][2] = As[m0 * AS_STRIDE + ks * 8 + tig + 4];
                af[mt][3] = As[(m0 + 8) * AS_STRIDE + ks * 8 + tig + 4];
            }
#pragma unroll
            for (int nt = 0; nt < NT; nt++) {
                int n0 = wn + nt * 8 + g;
                bf[nt][0] = Bs[(ks * 8 + tig) * BS_STRIDE + n0];
                bf[nt][1] = Bs[(ks * 8 + tig + 4) * BS_STRIDE + n0];
            }
#pragma unroll
            for (int mt = 0; mt < MT; mt++)
#pragma unroll
                for (int nt = 0; nt < NT; nt++)
                    mma_tf32(acc[mt][nt], af[mt], bf[nt]);
        }
        __syncthreads();
    }

    // ---- epilogue: fp16 store + fused attention dots ----
    const int head = (block_col + wn) >> 6;   // WN=32 fits inside one 64-wide head
    float2 asv[NT], adv[NT];
#pragma unroll
    for (int nt = 0; nt < NT; nt++) {
        int ci = (block_col + wn + nt * 8 + 2 * tig) & 63;
        asv[nt] = *(const float2*)&a_src[head * HID + ci];
        adv[nt] = *(const float2*)&a_dst[head * HID + ci];
    }

#pragma unroll
    for (int mt = 0; mt < MT; mt++) {
        int r0 = block_row + wm + mt * 16 + g;
        int r1 = r0 + 8;
        float ss0 = 0.f, sd0 = 0.f, ss1 = 0.f, sd1 = 0.f;
#pragma unroll
        for (int nt = 0; nt < NT; nt++) {
            const float* c = acc[mt][nt];
            int col = block_col + wn + nt * 8 + 2 * tig;
            if (r0 < M) *(__half2*)&Ch[(size_t)r0 * N + col] = __floats2half2_rn(c[0], c[1]);
            if (r1 < M) *(__half2*)&Ch[(size_t)r1 * N + col] = __floats2half2_rn(c[2], c[3]);
            ss0 += c[0] * asv[nt].x + c[1] * asv[nt].y;
            sd0 += c[0] * adv[nt].x + c[1] * adv[nt].y;
            ss1 += c[2] * asv[nt].x + c[3] * asv[nt].y;
            sd1 += c[2] * adv[nt].x + c[3] * adv[nt].y;
        }
        // reduce the 4 lanes (tig) that share these rows
#pragma unroll
        for (int o = 1; o < 4; o <<= 1) {
            ss0 += __shfl_xor_sync(0xffffffffu, ss0, o);
            sd0 += __shfl_xor_sync(0xffffffffu, sd0, o);
            ss1 += __shfl_xor_sync(0xffffffffu, ss1, o);
            sd1 += __shfl_xor_sync(0xffffffffu, sd1, o);
        }
        if (tig == 0) {
            if (r0 < M) {
                atomicAdd(&alsrc[r0 * HEADS + head], ss0);
                atomicAdd(&aldst[r0 * HEADS + head], sd0);
            }
            if (r1 < M) {
                atomicAdd(&alsrc[r1 * HEADS + head], ss1);
                atomicAdd(&aldst[r1 * HEADS + head], sd1);
            }
        }
    }
}

// ------------------------- layer1 edge softmax num/denominator ---------------
__global__ void edge_den1_kernel(const int* __restrict__ ei)
{
    int e = blockIdx.x * blockDim.x + threadIdx.x;
    if (e >= EP) return;
    int s, d;
    if (e < NEDGES) { s = ei[e]; d = ei[NEDGES + e]; }
    else            { s = d = e - NEDGES; }

    float4 s0 = *(const float4*)&g_alsrc1[(size_t)s * 8];
    float4 s1 = *(const float4*)&g_alsrc1[(size_t)s * 8 + 4];
    float4 d0 = *(const float4*)&g_aldst1[(size_t)d * 8];
    float4 d1 = *(const float4*)&g_aldst1[(size_t)d * 8 + 4];

    float v[8] = { s0.x + d0.x, s0.y + d0.y, s0.z + d0.z, s0.w + d0.w,
                   s1.x + d1.x, s1.y + d1.y, s1.z + d1.z, s1.w + d1.w };
    float exv[8];
#pragma unroll
    for (int h = 0; h < 8; h++) {
        float t = v[h];
        t = (t > 0.f) ? t : NEG_SLOPE * t;
        t = __expf(t);
        exv[h] = t;
        atomicAdd(&g_denom1[(size_t)d * 8 + h], t);
    }
    *(float4*)&g_ex1[(size_t)e * 8]     = make_float4(exv[0], exv[1], exv[2], exv[3]);
    *(float4*)&g_ex1[(size_t)e * 8 + 4] = make_float4(exv[4], exv[5], exv[6], exv[7]);
}

// ------------------------- layer1 message scatter (warp/edge, fp16 gather) ---
__global__ __launch_bounds__(256)
void scatter1_kernel(const int* __restrict__ ei)
{
    int warp_id = (blockIdx.x * blockDim.x + threadIdx.x) >> 5;
    int lane = threadIdx.x & 31;
    if (warp_id >= EP) return;
    int s, d;
    if (warp_id < NEDGES) { s = ei[warp_id]; d = ei[NEDGES + warp_id]; }
    else                  { s = d = warp_id - NEDGES; }

    const __half* hsrc = g_h1h + (size_t)s * H1DIM;
    float* odst = g_out1 + (size_t)d * H1DIM;
    const float* exe = g_ex1 + (size_t)warp_id * 8;
    const float* dnd = g_denom1 + (size_t)d * 8;

#pragma unroll
    for (int it = 0; it < 2; it++) {
        int q = it * 128 + lane * 4;        // half2 index (4 consecutive)
        int h = q >> 5;                     // head
        float alpha = __ldg(&exe[h]) / __ldg(&dnd[h]);
        uint4 raw = *(const uint4*)(hsrc + (size_t)q * 2);
        const __half2* hp = (const __half2*)&raw;
        float2 f0 = __half22float2(hp[0]);
        float2 f1 = __half22float2(hp[1]);
        float2 f2 = __half22float2(hp[2]);
        float2 f3 = __half22float2(hp[3]);
        red_add_v4(odst + q * 2,
                   make_float4(f0.x * alpha, f0.y * alpha, f1.x * alpha, f1.y * alpha));
        red_add_v4(odst + q * 2 + 4,
                   make_float4(f2.x * alpha, f2.y * alpha, f3.x * alpha, f3.y * alpha));
    }
}

// ------------------------- layer2 edge softmax --------------------------------
__global__ void edge_den2_kernel(const int* __restrict__ ei)
{
    int e = blockIdx.x * blockDim.x + threadIdx.x;
    if (e >= EP) return;
    int s, d;
    if (e < NEDGES) { s = ei[e]; d = ei[NEDGES + e]; }
    else            { s = d = e - NEDGES; }
    float t = g_alsrc2[s] + g_aldst2[d];
    t = (t > 0.f) ? t : NEG_SLOPE * t;
    t = __expf(t);
    g_ex2[e] = t;
    atomicAdd(&g_denom2[d], t);
}

// ------------------------- layer2 message scatter (16 thr/edge, fp16) --------
__global__ __launch_bounds__(256)
void scatter2_kernel(const int* __restrict__ ei)
{
    int gt = blockIdx.x * blockDim.x + threadIdx.x;
    int e  = gt >> 4;
    int l  = gt & 15;
    if (e >= EP) return;
    int s, d;
    if (e < NEDGES) { s = ei[e]; d = ei[NEDGES + e]; }
    else            { s = d = e - NEDGES; }
    float alpha = __ldg(&g_ex2[e]) / __ldg(&g_denom2[d]);
    uint2 raw = *(const uint2*)(g_h2h + (size_t)s * HID + l * 4);
    const __half2* hp = (const __half2*)&raw;
    float2 f0 = __half22float2(hp[0]);
    float2 f1 = __half22float2(hp[1]);
    red_add_v4(g_out2 + (size_t)d * HID + l * 4,
               make_float4(f0.x * alpha, f0.y * alpha, f1.x * alpha, f1.y * alpha));
}

// ------------------------- final: relu(out2+b2) @ Wc + bc ---------------------
__global__ void final_kernel(const float* __restrict__ b2,
                             const float* __restrict__ Wc,
                             const float* __restrict__ bc,
                             float* __restrict__ out)
{
    int warp = (blockIdx.x * blockDim.x + threadIdx.x) >> 5;
    int lane = threadIdx.x & 31;
    if (warp >= NNODES) return;
    float acc = 0.f;
#pragma unroll
    for (int k = lane; k < HID; k += 32) {
        float v = g_out2[(size_t)warp * HID + k] + b2[k];
        v = fmaxf(v, 0.f);
        acc += v * Wc[k];
    }
#pragma unroll
    for (int o = 16; o; o >>= 1) acc += __shfl_down_sync(0xffffffffu, acc, o);
    if (lane == 0) out[warp] = acc + bc[0];
}

// ------------------------- host launcher --------------------------------------
extern "C" void kernel_launch(void* const* d_in, const int* in_sizes, int n_in,
                              void* d_out, int out_size)
{
    const float* x      = (const float*)d_in[0];
    const int*   ei     = (const int*)d_in[1];     // int32 (JAX x64 disabled)
    const float* W1     = (const float*)d_in[2];
    const float* a_src1 = (const float*)d_in[3];
    const float* a_dst1 = (const float*)d_in[4];
    const float* b1     = (const float*)d_in[5];
    const float* W2     = (const float*)d_in[6];
    const float* a_src2 = (const float*)d_in[7];
    const float* a_dst2 = (const float*)d_in[8];
    const float* b2     = (const float*)d_in[9];
    const float* Wc     = (const float*)d_in[10];
    const float* bc     = (const float*)d_in[11];
    float* out = (float*)d_out;

    // symbol address lookup (host API, no device work; capture-safe)
    static __half* s_h1h = nullptr;
    static __half* s_h2h = nullptr;
    static float *s_out1 = nullptr, *s_alsrc1 = nullptr, *s_aldst1 = nullptr,
                 *s_alsrc2 = nullptr, *s_aldst2 = nullptr;
    if (!s_h1h) {
        cudaGetSymbolAddress((void**)&s_h1h,    g_h1h);
        cudaGetSymbolAddress((void**)&s_h2h,    g_h2h);
        cudaGetSymbolAddress((void**)&s_out1,   g_out1);
        cudaGetSymbolAddress((void**)&s_alsrc1, g_alsrc1);
        cudaGetSymbolAddress((void**)&s_aldst1, g_aldst1);
        cudaGetSymbolAddress((void**)&s_alsrc2, g_alsrc2);
        cudaGetSymbolAddress((void**)&s_aldst2, g_aldst2);
    }

    // zero accumulators
    zero_big_kernel<<<8192, 256>>>();
    zero_small_kernel<<<(NNODES * 8 + 255) / 256, 256>>>();

    // GEMM1: h1 = x @ W1  [50000,128]x[128,512]  (fp16 out + fused att dots)
    {
        dim3 grid(H1DIM / 128, (NNODES + 127) / 128);
        gemm_tf32_att<128, 128, 32, 64, 32, 8, false, FIN, H1DIM>
            <<<grid, 256>>>(NNODES, x, W1, nullptr, a_src1, a_dst1,
                            s_h1h, s_alsrc1, s_aldst1);
    }
    // edge softmax layer 1
    edge_den1_kernel<<<(EP + 255) / 256, 256>>>(ei);
    // scatter layer 1 (warp per edge, fp16 gather)
    scatter1_kernel<<<(EP * 32 + 255) / 256, 256>>>(ei);

    // GEMM2: h2 = relu(out1 + b1) @ W2  [50000,512]x[512,64]
    {
        dim3 grid(HID / 64, (NNODES + 127) / 128);
        gemm_tf32_att<128, 64, 32, 32, 32, 1, true, H1DIM, HID>
            <<<grid, 256>>>(NNODES, s_out1, W2, b1, a_src2, a_dst2,
                            s_h2h, s_alsrc2, s_aldst2);
    }
    // edge softmax layer 2
    edge_den2_kernel<<<(EP + 255) / 256, 256>>>(ei);
    // scatter layer 2 (16 threads per edge, fp16 gather)
    scatter2_kernel<<<(EP * 16 + 255) / 256, 256>>>(ei);

    // final projection
    final_kernel<<<(NNODES * 32 + 255) / 256, 256>>>(b2, Wc, bc, out);
}

// round 4
// speedup vs baseline: 2.3050x; 1.6734x over previous
#include <cuda_runtime.h>
#include <cuda_fp16.h>
#include <cstdint>

// Problem constants (fixed by the dataset)
#define NNODES 50000
#define NEDGES 400000
#define FIN    128
#define HID    64
#define H1DIM  512                 // 8 heads * 64
#define NEG_SLOPE 0.2f

// ------------------------- scratch (static device memory) -------------------
__device__ __half g_h1h[(size_t)NNODES * H1DIM];   // fp16 copy of x@W1
__device__ float  g_out1[(size_t)NNODES * H1DIM];  // layer1 aggregated (written once)
__device__ float  g_alsrc1[(size_t)NNODES * 8];
__device__ float  g_aldst1[(size_t)NNODES * 8];

__device__ __half g_h2h[(size_t)NNODES * HID];     // fp16 copy of layer2 features
__device__ float  g_alsrc2[NNODES];
__device__ float  g_aldst2[NNODES];

// CSR (dst-sorted incoming edges, self-loops excluded)
__device__ int g_cnt[NNODES];
__device__ int g_ptr[NNODES + 1];
__device__ int g_fill[NNODES];
__device__ int g_csrc[NEDGES];

// ------------------------- helpers ------------------------------------------
__device__ __forceinline__ uint32_t f2tf32(float f) {
    uint32_t r;
    asm("cvt.rna.tf32.f32 %0, %1;" : "=r"(r) : "f"(f));
    return r;
}

__device__ __forceinline__ void mma_tf32(float d[4], const uint32_t a[4], const uint32_t b[2]) {
    asm volatile(
        "mma.sync.aligned.m16n8k8.row.col.f32.tf32.tf32.f32 "
        "{%0,%1,%2,%3}, {%4,%5,%6,%7}, {%8,%9}, {%0,%1,%2,%3};"
        : "+f"(d[0]), "+f"(d[1]), "+f"(d[2]), "+f"(d[3])
        : "r"(a[0]), "r"(a[1]), "r"(a[2]), "r"(a[3]), "r"(b[0]), "r"(b[1]));
}

__device__ __forceinline__ float leaky_exp(float t) {
    t = (t > 0.f) ? t : NEG_SLOPE * t;
    return __expf(t);
}

// ------------------------- zero + CSR build ----------------------------------
__global__ void zero_small_kernel() {
    int i = blockIdx.x * blockDim.x + threadIdx.x;
    if (i < NNODES * 8) { g_alsrc1[i] = 0.f; g_aldst1[i] = 0.f; }
    if (i < NNODES)     { g_alsrc2[i] = 0.f; g_aldst2[i] = 0.f; g_cnt[i] = 0; }
}

__global__ void hist_kernel(const int* __restrict__ ei) {
    int e = blockIdx.x * blockDim.x + threadIdx.x;
    if (e >= NEDGES) return;
    atomicAdd(&g_cnt[ei[NEDGES + e]], 1);
}

// single-block exclusive scan over g_cnt -> g_ptr / g_fill
__global__ void scan_kernel() {
    __shared__ int sums[1024];
    const int T = 1024;
    const int tid = threadIdx.x;
    const int CH = (NNODES + T - 1) / T;   // 49
    const int base = tid * CH;
    int s = 0;
    for (int i = 0; i < CH; i++) {
        int idx = base + i;
        if (idx < NNODES) s += g_cnt[idx];
    }
    sums[tid] = s;
    __syncthreads();
    for (int off = 1; off < T; off <<= 1) {
        int v = (tid >= off) ? sums[tid - off] : 0;
        __syncthreads();
        sums[tid] += v;
        __syncthreads();
    }
    int run = (tid == 0) ? 0 : sums[tid - 1];
    for (int i = 0; i < CH; i++) {
        int idx = base + i;
        if (idx < NNODES) {
            g_ptr[idx] = run;
            g_fill[idx] = run;
            run += g_cnt[idx];
        }
    }
    if (tid == T - 1) g_ptr[NNODES] = run;
}

__global__ void fill_kernel(const int* __restrict__ ei) {
    int e = blockIdx.x * blockDim.x + threadIdx.x;
    if (e >= NEDGES) return;
    int s = ei[e];
    int d = ei[NEDGES + e];
    int pos = atomicAdd(&g_fill[d], 1);
    g_csrc[pos] = s;
}

// ------------------------- TF32 tensor-core GEMM with fused attention dots ---
// C[M,N] = op(A)[M,K] @ B[K,N];  op = relu(A + bias[k]) if RELU_BIAS.
// Writes fp16 C to Ch; accumulates per-(row,head) dot(a_src, C_row_head) into
// alsrc/aldst via atomics (must be pre-zeroed). HEADS = N/64.
template<int BM, int BN, int BK, int WM, int WN, int HEADS, bool RELU_BIAS, int K, int N>
__global__ __launch_bounds__(256)
void gemm_tf32_att(int M,
                   const float* __restrict__ A,
                   const float* __restrict__ B,
                   const float* __restrict__ bias,
                   const float* __restrict__ a_src,
                   const float* __restrict__ a_dst,
                   __half* __restrict__ Ch,
                   float* __restrict__ alsrc,
                   float* __restrict__ aldst)
{
    constexpr int WARPS_N = BN / WN;
    constexpr int MT = WM / 16;
    constexpr int NT = WN / 8;
    constexpr int AS_STRIDE = BK + 4;
    constexpr int BS_STRIDE = BN + 8;

    __shared__ uint32_t As[BM * AS_STRIDE];
    __shared__ uint32_t Bs[BK * BS_STRIDE];

    const int tid  = threadIdx.x;
    const int lane = tid & 31;
    const int warp = tid >> 5;
    const int block_row = blockIdx.y * BM;
    const int block_col = blockIdx.x * BN;
    const int wm = (warp / WARPS_N) * WM;
    const int wn = (warp % WARPS_N) * WN;
    const int g   = lane >> 2;
    const int tig = lane & 3;

    float acc[MT][NT][4];
#pragma unroll
    for (int mt = 0; mt < MT; mt++)
#pragma unroll
        for (int nt = 0; nt < NT; nt++)
#pragma unroll
            for (int j = 0; j < 4; j++) acc[mt][nt][j] = 0.f;

    for (int k0 = 0; k0 < K; k0 += BK) {
        constexpr int A_F4 = BM * BK / 1024;
#pragma unroll
        for (int i = 0; i < A_F4; i++) {
            int idx = i * 256 + tid;
            int ar  = idx / (BK / 4);
            int ac4 = idx % (BK / 4);
            int grow = block_row + ar;
            float4 v = make_float4(0.f, 0.f, 0.f, 0.f);
            if (grow < M) {
                v = *(const float4*)&A[(size_t)grow * K + k0 + ac4 * 4];
                if (RELU_BIAS) {
                    const float4 b = *(const float4*)&bias[k0 + ac4 * 4];
                    v.x = fmaxf(v.x + b.x, 0.f);
                    v.y = fmaxf(v.y + b.y, 0.f);
                    v.z = fmaxf(v.z + b.z, 0.f);
                    v.w = fmaxf(v.w + b.w, 0.f);
                }
            }
            uint4 t = make_uint4(f2tf32(v.x), f2tf32(v.y), f2tf32(v.z), f2tf32(v.w));
            *(uint4*)&As[ar * AS_STRIDE + ac4 * 4] = t;
        }
        constexpr int B_F4 = BK * BN / 1024;
#pragma unroll
        for (int i = 0; i < B_F4; i++) {
            int idx = i * 256 + tid;
            int br  = idx / (BN / 4);
            int bc4 = idx % (BN / 4);
            float4 v = *(const float4*)&B[(size_t)(k0 + br) * N + block_col + bc4 * 4];
            uint4 t = make_uint4(f2tf32(v.x), f2tf32(v.y), f2tf32(v.z), f2tf32(v.w));
            *(uint4*)&Bs[br * BS_STRIDE + bc4 * 4] = t;
        }
        __syncthreads();

#pragma unroll
        for (int ks = 0; ks < BK / 8; ks++) {
            uint32_t af[MT][4], bf[NT][2];
#pragma unroll
            for (int mt = 0; mt < MT; mt++) {
                int m0 = wm + mt * 16 + g;
                af[mt][0] = As[m0 * AS_STRIDE + ks * 8 + tig];
                af[mt][1] = As[(m0 + 8) * AS_STRIDE + ks * 8 + tig];
                af[mt][2] = As[m0 * AS_STRIDE + ks * 8 + tig + 4];
                af[mt][3] = As[(m0 + 8) * AS_STRIDE + ks * 8 + tig + 4];
            }
#pragma unroll
            for (int nt = 0; nt < NT; nt++) {
                int n0 = wn + nt * 8 + g;
                bf[nt][0] = Bs[(ks * 8 + tig) * BS_STRIDE + n0];
                bf[nt][1] = Bs[(ks * 8 + tig + 4) * BS_STRIDE + n0];
            }
#pragma unroll
            for (int mt = 0; mt < MT; mt++)
#pragma unroll
                for (int nt = 0; nt < NT; nt++)
                    mma_tf32(acc[mt][nt], af[mt], bf[nt]);
        }
        __syncthreads();
    }

    // epilogue: fp16 store + fused attention dots
    const int head = (block_col + wn) >> 6;
    float2 asv[NT], adv[NT];
#pragma unroll
    for (int nt = 0; nt < NT; nt++) {
        int ci = (block_col + wn + nt * 8 + 2 * tig) & 63;
        asv[nt] = *(const float2*)&a_src[head * HID + ci];
        adv[nt] = *(const float2*)&a_dst[head * HID + ci];
    }

#pragma unroll
    for (int mt = 0; mt < MT; mt++) {
        int r0 = block_row + wm + mt * 16 + g;
        int r1 = r0 + 8;
        float ss0 = 0.f, sd0 = 0.f, ss1 = 0.f, sd1 = 0.f;
#pragma unroll
        for (int nt = 0; nt < NT; nt++) {
            const float* c = acc[mt][nt];
            int col = block_col + wn + nt * 8 + 2 * tig;
            if (r0 < M) *(__half2*)&Ch[(size_t)r0 * N + col] = __floats2half2_rn(c[0], c[1]);
            if (r1 < M) *(__half2*)&Ch[(size_t)r1 * N + col] = __floats2half2_rn(c[2], c[3]);
            ss0 += c[0] * asv[nt].x + c[1] * asv[nt].y;
            sd0 += c[0] * adv[nt].x + c[1] * adv[nt].y;
            ss1 += c[2] * asv[nt].x + c[3] * asv[nt].y;
            sd1 += c[2] * adv[nt].x + c[3] * adv[nt].y;
        }
#pragma unroll
        for (int o = 1; o < 4; o <<= 1) {
            ss0 += __shfl_xor_sync(0xffffffffu, ss0, o);
            sd0 += __shfl_xor_sync(0xffffffffu, sd0, o);
            ss1 += __shfl_xor_sync(0xffffffffu, ss1, o);
            sd1 += __shfl_xor_sync(0xffffffffu, sd1, o);
        }
        if (tig == 0) {
            if (r0 < M) {
                atomicAdd(&alsrc[r0 * HEADS + head], ss0);
                atomicAdd(&aldst[r0 * HEADS + head], sd0);
            }
            if (r1 < M) {
                atomicAdd(&alsrc[r1 * HEADS + head], ss1);
                atomicAdd(&aldst[r1 * HEADS + head], sd1);
            }
        }
    }
}

// ------------------------- layer1 aggregation (warp per dst node) ------------
// Fuses edge softmax + message aggregation: out1[d] = (sum_e ex_e * h1[src_e]) / (sum_e ex_e)
// Self-loop handled analytically. No atomics, no denominators, no zeroing.
__global__ __launch_bounds__(256)
void agg1_kernel()
{
    int d    = (blockIdx.x * blockDim.x + threadIdx.x) >> 5;
    int lane = threadIdx.x & 31;
    if (d >= NNODES) return;
    const int head = lane >> 2;            // lane owns cols [lane*16, lane*16+16) -> one head

    const float adst = g_aldst1[(size_t)d * 8 + head];

    float acc[16];
    float den;
    // self-loop
    {
        float ex = leaky_exp(g_alsrc1[(size_t)d * 8 + head] + adst);
        den = ex;
        const __half* hp = g_h1h + (size_t)d * H1DIM + lane * 16;
        uint4 r0 = *(const uint4*)hp;
        uint4 r1 = *(const uint4*)(hp + 8);
        const __half2* a = (const __half2*)&r0;
        const __half2* b = (const __half2*)&r1;
#pragma unroll
        for (int i = 0; i < 4; i++) {
            float2 f = __half22float2(a[i]);
            acc[2*i]   = ex * f.x;
            acc[2*i+1] = ex * f.y;
            float2 g2 = __half22float2(b[i]);
            acc[8+2*i]   = ex * g2.x;
            acc[8+2*i+1] = ex * g2.y;
        }
    }

    const int beg = g_ptr[d], end = g_ptr[d + 1];
    for (int j = beg; j < end; j++) {
        int s = g_csrc[j];
        float ex = leaky_exp(g_alsrc1[(size_t)s * 8 + head] + adst);
        den += ex;
        const __half* hp = g_h1h + (size_t)s * H1DIM + lane * 16;
        uint4 r0 = *(const uint4*)hp;
        uint4 r1 = *(const uint4*)(hp + 8);
        const __half2* a = (const __half2*)&r0;
        const __half2* b = (const __half2*)&r1;
#pragma unroll
        for (int i = 0; i < 4; i++) {
            float2 f = __half22float2(a[i]);
            acc[2*i]   += ex * f.x;
            acc[2*i+1] += ex * f.y;
            float2 g2 = __half22float2(b[i]);
            acc[8+2*i]   += ex * g2.x;
            acc[8+2*i+1] += ex * g2.y;
        }
    }

    float inv = __frcp_rn(den);
    float* op = g_out1 + (size_t)d * H1DIM + lane * 16;
#pragma unroll
    for (int q = 0; q < 4; q++) {
        float4 v = make_float4(acc[4*q] * inv, acc[4*q+1] * inv,
                               acc[4*q+2] * inv, acc[4*q+3] * inv);
        *(float4*)(op + 4*q) = v;
    }
}

// ------------------------- layer2 aggregation + final projection -------------
// out[d] = relu(agg2[d] + b2) @ Wc + bc, agg2 computed like agg1 (1 head, 64 cols)
__global__ __launch_bounds__(256)
void agg2_final_kernel(const float* __restrict__ b2,
                       const float* __restrict__ Wc,
                       const float* __restrict__ bc,
                       float* __restrict__ out)
{
    int d    = (blockIdx.x * blockDim.x + threadIdx.x) >> 5;
    int lane = threadIdx.x & 31;
    if (d >= NNODES) return;
    const int c0 = lane * 2;

    const float adst = g_aldst2[d];

    float acc0, acc1, den;
    {
        float ex = leaky_exp(g_alsrc2[d] + adst);
        den = ex;
        float2 f = __half22float2(*(const __half2*)(g_h2h + (size_t)d * HID + c0));
        acc0 = ex * f.x;
        acc1 = ex * f.y;
    }

    const int beg = g_ptr[d], end = g_ptr[d + 1];
    for (int j = beg; j < end; j++) {
        int s = g_csrc[j];
        float ex = leaky_exp(g_alsrc2[s] + adst);
        den += ex;
        float2 f = __half22float2(*(const __half2*)(g_h2h + (size_t)s * HID + c0));
        acc0 += ex * f.x;
        acc1 += ex * f.y;
    }

    float inv = __frcp_rn(den);
    float v0 = fmaxf(acc0 * inv + b2[c0],     0.f) * Wc[c0];
    float v1 = fmaxf(acc1 * inv + b2[c0 + 1], 0.f) * Wc[c0 + 1];
    float r = v0 + v1;
#pragma unroll
    for (int o = 16; o; o >>= 1) r += __shfl_down_sync(0xffffffffu, r, o);
    if (lane == 0) out[d] = r + bc[0];
}

// ------------------------- host launcher --------------------------------------
extern "C" void kernel_launch(void* const* d_in, const int* in_sizes, int n_in,
                              void* d_out, int out_size)
{
    const float* x      = (const float*)d_in[0];
    const int*   ei     = (const int*)d_in[1];     // int32 (JAX x64 disabled)
    const float* W1     = (const float*)d_in[2];
    const float* a_src1 = (const float*)d_in[3];
    const float* a_dst1 = (const float*)d_in[4];
    const float* b1     = (const float*)d_in[5];
    const float* W2     = (const float*)d_in[6];
    const float* a_src2 = (const float*)d_in[7];
    const float* a_dst2 = (const float*)d_in[8];
    const float* b2     = (const float*)d_in[9];
    const float* Wc     = (const float*)d_in[10];
    const float* bc     = (const float*)d_in[11];
    float* out = (float*)d_out;

    static __half* s_h1h = nullptr;
    static __half* s_h2h = nullptr;
    static float *s_out1 = nullptr, *s_alsrc1 = nullptr, *s_aldst1 = nullptr,
                 *s_alsrc2 = nullptr, *s_aldst2 = nullptr;
    if (!s_h1h) {  // address lookup only; no device work; capture-safe
        cudaGetSymbolAddress((void**)&s_h1h,    g_h1h);
        cudaGetSymbolAddress((void**)&s_h2h,    g_h2h);
        cudaGetSymbolAddress((void**)&s_out1,   g_out1);
        cudaGetSymbolAddress((void**)&s_alsrc1, g_alsrc1);
        cudaGetSymbolAddress((void**)&s_aldst1, g_aldst1);
        cudaGetSymbolAddress((void**)&s_alsrc2, g_alsrc2);
        cudaGetSymbolAddress((void**)&s_aldst2, g_aldst2);
    }

    // zero attention accumulators + CSR counters
    zero_small_kernel<<<(NNODES * 8 + 255) / 256, 256>>>();
    // CSR build (dst histogram -> exclusive scan -> fill)
    hist_kernel<<<(NEDGES + 255) / 256, 256>>>(ei);
    scan_kernel<<<1, 1024>>>();
    fill_kernel<<<(NEDGES + 255) / 256, 256>>>(ei);

    // GEMM1: h1 = x @ W1  [50000,128]x[128,512]  (fp16 out + fused att dots)
    {
        dim3 grid(H1DIM / 128, (NNODES + 127) / 128);
        gemm_tf32_att<128, 128, 32, 64, 32, 8, false, FIN, H1DIM>
            <<<grid, 256>>>(NNODES, x, W1, nullptr, a_src1, a_dst1,
                            s_h1h, s_alsrc1, s_aldst1);
    }
    // layer1: fused edge softmax + aggregation (warp per node)
    agg1_kernel<<<(NNODES * 32 + 255) / 256, 256>>>();

    // GEMM2: h2 = relu(out1 + b1) @ W2  [50000,512]x[512,64]
    {
        dim3 grid(HID / 64, (NNODES + 127) / 128);
        gemm_tf32_att<128, 64, 32, 32, 32, 1, true, H1DIM, HID>
            <<<grid, 256>>>(NNODES, s_out1, W2, b1, a_src2, a_dst2,
                            s_h2h, s_alsrc2, s_aldst2);
    }
    // layer2: fused edge softmax + aggregation + final projection
    agg2_final_kernel<<<(NNODES * 32 + 255) / 256, 256>>>(b2, Wc, bc, out);
}